// round 6
// baseline (speedup 1.0000x reference)
#include <cuda_runtime.h>
#include <cstdint>

// Problem constants
#define BATCH 128
#define TT    512
#define NBLK  128          // persistent grid: 64 column-tiles x 2 K-halves
#define NTHR  256          // 8 warps, warp tile 32x32 on a 128x64 CTA tile
#define SP    68           // smem row pitch (words): conflict-free LDS.64
#define STAGE_B  52224u    // A 128*68*4 + B 64*68*4
#define STAGE_W  13056     // words
#define BOFF_B   34816u    // byte offset of B region in a stage
#define BOFF_W   8704

// ---------------- device scratch (static, allocation-free) ----------------
__device__ __align__(16) float g_z[BATCH * 1024];        // fc output (tf32, k-permuted)
__device__ __align__(16) float g_h1[2][BATCH * 1024];    // layer-0 hidden
__device__ __align__(16) float g_h2[2][BATCH * 1024];    // layer-1 hidden
__device__ __align__(16) float g_wpack[4u * 64u * 16u * 4096u];  // packed tf32 weights, 64MB
__device__ __align__(16) float g_xch[64][2][BATCH * 64]; // pair partial-exchange, 4MB
__device__ unsigned g_xflag[64][2][2];                   // exchange counters
__device__ unsigned g_bar_count;
__device__ volatile unsigned g_bar_gen;

// perm of low-3 bits: puts (k, k+4) adjacent -> LDS.64 fragment pairs
__device__ __host__ __forceinline__ int perm8(int i) { return ((i & 3) << 1) | ((i >> 2) & 1); }

// ---------------- helpers ----------------
__device__ __forceinline__ unsigned f2tf32(float x) {
    unsigned r;
    asm("cvt.rna.tf32.f32 %0, %1;" : "=r"(r) : "f"(x));
    return r;
}
__device__ __forceinline__ float rtf(float x) { return __uint_as_float(f2tf32(x)); }

__device__ __forceinline__ void mma_tf32(float c[4], unsigned a0, unsigned a1,
                                         unsigned a2, unsigned a3,
                                         unsigned b0, unsigned b1) {
    asm volatile(
        "mma.sync.aligned.m16n8k8.row.col.f32.tf32.tf32.f32 "
        "{%0,%1,%2,%3}, {%4,%5,%6,%7}, {%8,%9}, {%0,%1,%2,%3};"
        : "+f"(c[0]), "+f"(c[1]), "+f"(c[2]), "+f"(c[3])
        : "r"(a0), "r"(a1), "r"(a2), "r"(a3), "r"(b0), "r"(b1));
}

__device__ __forceinline__ void cp16(unsigned dst, const void* src) {
    asm volatile("cp.async.cg.shared.global [%0], [%1], 16;\n" :: "r"(dst), "l"(src));
}
#define CP_COMMIT() asm volatile("cp.async.commit_group;\n" ::: "memory")
#define CP_WAIT1()  asm volatile("cp.async.wait_group 1;\n" ::: "memory")

__device__ __forceinline__ float sigf(float x) { return 1.0f / (1.0f + __expf(-x)); }
__device__ __forceinline__ float tanh_fast(float x) {
    float e = __expf(2.0f * x);
    return 1.0f - 2.0f / (e + 1.0f);
}

// ---------------- software grid barrier ----------------
__device__ __forceinline__ void grid_barrier() {
    __threadfence();
    __syncthreads();
    if (threadIdx.x == 0) {
        unsigned gen = g_bar_gen;
        if (atomicAdd(&g_bar_count, 1u) == NBLK - 1) {
            *(volatile unsigned*)&g_bar_count = 0;
            __threadfence();
            g_bar_gen = gen + 1;
        } else {
            while (g_bar_gen == gen) {}
        }
        __threadfence();
    }
    __syncthreads();
}

// ---------------- init ----------------
__global__ void init_zero_kernel() {
    int idx = blockIdx.x * 256 + threadIdx.x;
    if (idx < BATCH * 1024 * 2) {
        (&g_h1[0][0])[idx] = 0.0f;
        (&g_h2[0][0])[idx] = 0.0f;
    }
    if (idx < 256) (&g_xflag[0][0][0])[idx] = 0;
    if (idx == 0) { g_bar_count = 0; g_bar_gen = 0; }
}

// ---------------- weight pre-pack (R4 layout, unchanged) ----------------
// wpack[mat][nb][kc16][rr64][kk64-permuted]; rr: gate=(rr>>3)&3, jloc=(rr&7)+((rr>>5)<<3)
__global__ void pack_kernel(const float* __restrict__ W0, const float* __restrict__ W1,
                            const float* __restrict__ W2, const float* __restrict__ W3) {
    int idx = blockIdx.x * 256 + threadIdx.x;   // 65536 blocks
    int kk  = idx & 63;
    int rr  = (idx >> 6) & 63;
    int kc  = (idx >> 12) & 15;
    int nb  = (idx >> 16) & 63;
    int mat = idx >> 22;
    const float* W = (mat == 0) ? W0 : (mat == 1) ? W1 : (mat == 2) ? W2 : W3;
    int gate = (rr >> 3) & 3;
    int jloc = (rr & 7) + ((rr >> 5) << 3);
    int srow = gate * 1024 + nb * 16 + jloc;
    float v = W[srow * 1024 + kc * 64 + kk];
    int kkp = (kk & ~7) | perm8(kk & 7);
    g_wpack[(((size_t)(mat * 64 + nb) * 16 + kc) << 12) + rr * 64 + kkp] = rtf(v);
}

// ---------------- fc: z = x @ fc_w^T + fc_b (tf32, k-permuted) ----------------
__global__ void fc_kernel(const float* __restrict__ x, const float* __restrict__ fcw,
                          const float* __restrict__ fcb) {
    int idx = blockIdx.x * 256 + threadIdx.x;
    int b = idx >> 10, i = idx & 1023;
    const float4* xr = reinterpret_cast<const float4*>(x + b * 256);
    const float4* wr = reinterpret_cast<const float4*>(fcw + i * 256);
    float s = fcb[i];
    #pragma unroll 8
    for (int o = 0; o < 64; o++) {
        float4 xv = __ldg(xr + o), wv = __ldg(wr + o);
        s += xv.x * wv.x + xv.y * wv.y + xv.z * wv.z + xv.w * wv.w;
    }
    int ip = (i & ~7) | perm8(i & 7);
    g_z[b * 1024 + ip] = rtf(s);
}

// ---------------- tile compute: warp 32x32 of CTA 128x64, k=64 ----------------
__device__ __forceinline__ void tile_compute(const unsigned* __restrict__ as,
                                             const unsigned* __restrict__ bs,
                                             float acc[2][4][4],
                                             int wm, int wn, int grp, int tig) {
    const unsigned* pa = as + (wm * 32 + grp) * SP + 2 * tig;
    const unsigned* pb = bs + (wn * 32 + grp) * SP + 2 * tig;
    uint2 a[2][2], b[4];
    #pragma unroll
    for (int mi = 0; mi < 2; mi++) {
        a[mi][0] = *(const uint2*)(pa + mi * 16 * SP);
        a[mi][1] = *(const uint2*)(pa + (mi * 16 + 8) * SP);
    }
    #pragma unroll
    for (int nj = 0; nj < 4; nj++) b[nj] = *(const uint2*)(pb + nj * 8 * SP);

    #pragma unroll
    for (int k8 = 0; k8 < 8; k8++) {
        uint2 na[2][2], nb2[4];
        if (k8 < 7) {
            const unsigned* qa = pa + (k8 + 1) * 8;
            const unsigned* qb = pb + (k8 + 1) * 8;
            #pragma unroll
            for (int mi = 0; mi < 2; mi++) {
                na[mi][0] = *(const uint2*)(qa + mi * 16 * SP);
                na[mi][1] = *(const uint2*)(qa + (mi * 16 + 8) * SP);
            }
            #pragma unroll
            for (int nj = 0; nj < 4; nj++) nb2[nj] = *(const uint2*)(qb + nj * 8 * SP);
        }
        #pragma unroll
        for (int mi = 0; mi < 2; mi++)
            #pragma unroll
            for (int nj = 0; nj < 4; nj++)
                mma_tf32(acc[mi][nj], a[mi][0].x, a[mi][1].x, a[mi][0].y, a[mi][1].y,
                         b[nj].x, b[nj].y);
        if (k8 < 7) {
            #pragma unroll
            for (int mi = 0; mi < 2; mi++) { a[mi][0] = na[mi][0]; a[mi][1] = na[mi][1]; }
            #pragma unroll
            for (int nj = 0; nj < 4; nj++) b[nj] = nb2[nj];
        }
    }
}

// ---------------- GEMM: acc[128x64] += A[128, kbase + 64*nIter] @ B^T ----------------
__device__ __forceinline__ void gemm_phase(
    float acc[2][4][4], const float* __restrict__ A, int kbase,
    const float* __restrict__ Bb, int nIter,
    unsigned sb, const unsigned* shp,
    int tid, int wm, int wn, int grp, int tig)
{
    #pragma unroll
    for (int mi = 0; mi < 2; mi++)
        #pragma unroll
        for (int nj = 0; nj < 4; nj++)
            #pragma unroll
            for (int r = 0; r < 4; r++) acc[mi][nj][r] = 0.0f;

    #define ISSUE(s) do {                                                        \
        unsigned a_ = sb + (unsigned)((s) % 3) * STAGE_B;                        \
        const float* Ab_ = A + kbase + (s) * 64;                                 \
        const float* Bt_ = Bb + (size_t)(s) * 4096;                              \
        _Pragma("unroll")                                                        \
        for (int v = 0; v < 8; v++) {                                            \
            int idx = tid + (v << 8);                                            \
            int row = idx >> 4, c = idx & 15;                                    \
            cp16(a_ + row * 272 + c * 16, Ab_ + row * 1024 + c * 4);             \
        }                                                                        \
        _Pragma("unroll")                                                        \
        for (int v = 0; v < 4; v++) {                                            \
            int idx = tid + (v << 8);                                            \
            int row = idx >> 4, c = idx & 15;                                    \
            cp16(a_ + BOFF_B + row * 272 + c * 16, Bt_ + row * 64 + c * 4);      \
        }                                                                        \
    } while (0)

    ISSUE(0); CP_COMMIT();
    ISSUE(1); CP_COMMIT();

    for (int it = 0; it < nIter; it++) {
        CP_WAIT1();
        __syncthreads();
        const unsigned* st = shp + (it % 3) * STAGE_W;
        tile_compute(st, st + BOFF_W, acc, wm, wn, grp, tig);
        if (it + 2 < nIter) ISSUE(it + 2);
        CP_COMMIT();
    }
    #undef ISSUE
}

// ---------------- pair exchange: sum split-K partials through L2 ----------------
__device__ __forceinline__ void exchange_sum(
    float acc[2][4][4], bool ew, int kh, int nb, int slot, unsigned cnt,
    int wm, int wn, int grp, int tig)
{
    float* buf = g_xch[nb][slot];
    if (!ew) {
        #pragma unroll
        for (int mi = 0; mi < 2; mi++)
            #pragma unroll
            for (int nj = 0; nj < 4; nj++)
                #pragma unroll
                for (int rh = 0; rh < 2; rh++) {
                    int row = wm * 32 + mi * 16 + grp + rh * 8;
                    int col = wn * 32 + nj * 8 + 2 * tig;
                    __stcg(reinterpret_cast<float2*>(&buf[row * 64 + col]),
                           make_float2(acc[mi][nj][rh * 2], acc[mi][nj][rh * 2 + 1]));
                }
    }
    __syncthreads();
    if (threadIdx.x == 0) {
        __threadfence();
        atomicAdd(&g_xflag[nb][slot][kh], 1u);
        while (atomicAdd(&g_xflag[nb][slot][kh ^ 1], 0u) < cnt) {}
    }
    __syncthreads();
    if (ew) {
        #pragma unroll
        for (int mi = 0; mi < 2; mi++)
            #pragma unroll
            for (int nj = 0; nj < 4; nj++)
                #pragma unroll
                for (int rh = 0; rh < 2; rh++) {
                    int row = wm * 32 + mi * 16 + grp + rh * 8;
                    int col = wn * 32 + nj * 8 + 2 * tig;
                    float2 v = __ldcg(reinterpret_cast<const float2*>(&buf[row * 64 + col]));
                    acc[mi][nj][rh * 2]     += v.x;
                    acc[mi][nj][rh * 2 + 1] += v.y;
                }
    }
}

// ---------------- persistent LSTM kernel ----------------
__global__ void __launch_bounds__(NTHR, 1)
lstm_persistent(const float* __restrict__ bih0, const float* __restrict__ bhh0,
                const float* __restrict__ bih1, const float* __restrict__ bhh1,
                float* __restrict__ out)
{
    extern __shared__ unsigned sh[];
    const unsigned sb = (unsigned)__cvta_generic_to_shared(sh);

    const int tid  = threadIdx.x;
    const int warp = tid >> 5, lane = tid & 31;
    const int grp  = lane >> 2, tig = lane & 3;
    const int wm   = warp >> 1, wn = warp & 1;
    const int kh = blockIdx.x & 1;        // K-half
    const int nb = blockIdx.x >> 1;       // 16-column block of j (0..63)
    const bool ew = ((wm >> 1) == kh);    // this warp does EW for its own rows

    const float* W0  = g_wpack + (((size_t)(0 * 64 + nb) * 16 + kh * 8) << 12);  // Wih0 half
    const float* W1  = g_wpack + (((size_t)(1 * 64 + nb) * 16 + kh * 8) << 12);  // Whh0 half
    const float* WL1 = g_wpack + (((size_t)((2 + kh) * 64 + nb) * 16) << 12);    // Wih1/Whh1

    float acc[2][4][4];
    float gx[2][4][4];      // layer-0 input gates + biases (EW warps only)
    float b1s[4][2];        // layer-1 bias sums (per gate, col parity)
    float c1r[8], c2r[8];
    #pragma unroll
    for (int i = 0; i < 8; i++) { c1r[i] = 0.0f; c2r[i] = 0.0f; }
    unsigned x0 = 0, x1 = 0;

    // prologue: gx = z @ Wih0^T + bih0 + bhh0
    gemm_phase(acc, g_z, kh * 512, W0, 8, sb, sh, tid, wm, wn, grp, tig);
    exchange_sum(acc, ew, kh, nb, 0, ++x0, wm, wn, grp, tig);
    if (ew) {
        #pragma unroll
        for (int mi = 0; mi < 2; mi++)
            #pragma unroll
            for (int nj = 0; nj < 4; nj++)
                #pragma unroll
                for (int r = 0; r < 4; r++) {
                    int gidx = nj * 1024 + nb * 16 + wn * 8 + 2 * tig + (r & 1);
                    gx[mi][nj][r] = acc[mi][nj][r] + __ldg(bih0 + gidx) + __ldg(bhh0 + gidx);
                }
        #pragma unroll
        for (int nj = 0; nj < 4; nj++)
            #pragma unroll
            for (int c = 0; c < 2; c++) {
                int gidx = nj * 1024 + nb * 16 + wn * 8 + 2 * tig + c;
                b1s[nj][c] = __ldg(bih1 + gidx) + __ldg(bhh1 + gidx);
            }
    }
    grid_barrier();

    const int jb = nb * 16 + wn * 8;   // logical j-group base (8-aligned)

    for (int t = 0; t < TT; t++) {
        const int q = t & 1, p = q ^ 1;

        // ---- layer 0: h1_prev @ Whh0^T (+gx) -> h1[q], c1 ----
        gemm_phase(acc, g_h1[p], kh * 512, W1, 8, sb, sh, tid, wm, wn, grp, tig);
        exchange_sum(acc, ew, kh, nb, 0, ++x0, wm, wn, grp, tig);
        if (ew) {
            #pragma unroll
            for (int mi = 0; mi < 2; mi++)
                #pragma unroll
                for (int r = 0; r < 4; r++) {
                    float si = acc[mi][0][r] + gx[mi][0][r];
                    float sf = acc[mi][1][r] + gx[mi][1][r];
                    float sg = acc[mi][2][r] + gx[mi][2][r];
                    float so = acc[mi][3][r] + gx[mi][3][r];
                    int cell = mi * 4 + r;
                    float cv = sigf(sf) * c1r[cell] + sigf(si) * tanh_fast(sg);
                    c1r[cell] = cv;
                    float h = sigf(so) * tanh_fast(cv);
                    int row = wm * 32 + mi * 16 + grp + ((r & 2) ? 8 : 0);
                    int s3 = 2 * tig + (r & 1);
                    __stcg(&g_h1[q][row * 1024 + jb + perm8(s3)], rtf(h));
                }
        }
        grid_barrier();   // the single per-timestep grid sync

        // ---- layer 1: h1[q]@Wih1^T (kh=0) + h2[p]@Whh1^T (kh=1) -> h2[q], c2, out ----
        gemm_phase(acc, kh ? g_h2[p] : g_h1[q], 0, WL1, 16, sb, sh,
                   tid, wm, wn, grp, tig);
        exchange_sum(acc, ew, kh, nb, 1, ++x1, wm, wn, grp, tig);
        if (ew) {
            #pragma unroll
            for (int mi = 0; mi < 2; mi++)
                #pragma unroll
                for (int rh = 0; rh < 2; rh++) {
                    float hv[2];
                    #pragma unroll
                    for (int c = 0; c < 2; c++) {
                        int r = rh * 2 + c;
                        float si = acc[mi][0][r] + b1s[0][c];
                        float sf = acc[mi][1][r] + b1s[1][c];
                        float sg = acc[mi][2][r] + b1s[2][c];
                        float so = acc[mi][3][r] + b1s[3][c];
                        int cell = mi * 4 + r;
                        float cv = sigf(sf) * c2r[cell] + sigf(si) * tanh_fast(sg);
                        c2r[cell] = cv;
                        float h = sigf(so) * tanh_fast(cv);
                        hv[c] = h;
                        int row = wm * 32 + mi * 16 + grp + rh * 8;
                        int s3 = 2 * tig + c;
                        __stcg(&g_h2[q][row * 1024 + jb + perm8(s3)], rtf(h));
                    }
                    int row = wm * 32 + mi * 16 + grp + rh * 8;
                    *reinterpret_cast<float2*>(
                        out + ((size_t)row * TT + t) * 1024 + jb + 2 * tig) =
                        make_float2(hv[0], hv[1]);
                }
        }
    }
}

// ---------------- launch ----------------
extern "C" void kernel_launch(void* const* d_in, const int* in_sizes, int n_in,
                              void* d_out, int out_size) {
    const float* x    = (const float*)d_in[0];
    const float* fc_w = (const float*)d_in[1];
    const float* fc_b = (const float*)d_in[2];
    const float* Wih0 = (const float*)d_in[3];
    const float* Whh0 = (const float*)d_in[4];
    const float* bih0 = (const float*)d_in[5];
    const float* bhh0 = (const float*)d_in[6];
    const float* Wih1 = (const float*)d_in[7];
    const float* Whh1 = (const float*)d_in[8];
    const float* bih1 = (const float*)d_in[9];
    const float* bhh1 = (const float*)d_in[10];
    float* out = (float*)d_out;

    static int smem_set = 0;
    const int smem_bytes = 3 * STAGE_B;   // 156672
    if (!smem_set) {
        cudaFuncSetAttribute(lstm_persistent,
                             cudaFuncAttributeMaxDynamicSharedMemorySize, smem_bytes);
        smem_set = 1;
    }

    init_zero_kernel<<<1024, 256>>>();
    pack_kernel<<<65536, 256>>>(Wih0, Whh0, Wih1, Whh1);
    fc_kernel<<<512, 256>>>(x, fc_w, fc_b);
    lstm_persistent<<<NBLK, NTHR, smem_bytes>>>(bih0, bhh0, bih1, bhh1, out);
}